// round 3
// baseline (speedup 1.0000x reference)
#include <cuda_runtime.h>

#define SB   32      // S*B
#define NTOK 2048    // N
#define KK   16      // K
#define DD   32      // D
#define HH   128     // H

#define TPB  128     // threads per block
#define TOKPB 32     // tokens per block (4 threads per token)

typedef unsigned long long u64;

// Scratch for hk[k,h] + b1[h] per (s,b). 32*16*128 floats = 256 KB.
__device__ float g_hkb[SB * KK * HH];

__device__ __forceinline__ float tanhfast(float v) {
    float y;
    asm("tanh.approx.f32 %0, %1;" : "=f"(y) : "f"(v));
    return y;
}
__device__ __forceinline__ u64 pk2(float lo, float hi) {
    u64 r; asm("mov.b64 %0, {%1, %2};" : "=l"(r) : "f"(lo), "f"(hi)); return r;
}
__device__ __forceinline__ void upk2(float& lo, float& hi, u64 v) {
    asm("mov.b64 {%0, %1}, %2;" : "=f"(lo), "=f"(hi) : "l"(v));
}
__device__ __forceinline__ u64 add2(u64 a, u64 b) {
    u64 r; asm("add.rn.f32x2 %0, %1, %2;" : "=l"(r) : "l"(a), "l"(b)); return r;
}
__device__ __forceinline__ u64 fma2(u64 a, u64 b, u64 c) {
    u64 r; asm("fma.rn.f32x2 %0, %1, %2, %3;" : "=l"(r) : "l"(a), "l"(b), "l"(c)); return r;
}

// ---------------------------------------------------------------------------
// Prep: hkb[sb,k,h] = sum_d mu[sb,k,d]*Wm[d,h] + tau[sb,k,d]*Wt[d,h] + b1[h]
// ---------------------------------------------------------------------------
__global__ void prep_kernel(const float* __restrict__ mu,
                            const float* __restrict__ tau,
                            const float* __restrict__ W1,
                            const float* __restrict__ b1) {
    int k  = blockIdx.x;
    int sb = blockIdx.y;
    int h  = threadIdx.x;
    const float* mur  = mu  + (sb * KK + k) * DD;
    const float* taur = tau + (sb * KK + k) * DD;
    float s = b1[h];
    #pragma unroll
    for (int d = 0; d < DD; d++) {
        s = fmaf(mur [d], W1[(DD     + d) * HH + h], s);
        s = fmaf(taur[d], W1[(2 * DD + d) * HH + h], s);
    }
    g_hkb[(sb * KK + k) * HH + h] = s;
}

// ---------------------------------------------------------------------------
// Main: 4 threads per token, each owning an h-slice of 32 (2 chunks of 16).
// acc[16] combined across the 4 lanes via shfl_xor butterfly; each lane
// writes a 4-wide quarter of the softmax output (coalesced float4).
// ---------------------------------------------------------------------------
__global__ __launch_bounds__(TPB, 5)
void main_kernel(const float* __restrict__ x,
                 const float* __restrict__ W1,
                 const float* __restrict__ W2,
                 float* __restrict__ out) {
    __shared__ float Wx_s[DD * HH];   // 16 KB
    __shared__ float hkb_s[KK * HH];  //  8 KB
    __shared__ float w2_s[HH];        // 0.5 KB

    const int tid  = threadIdx.x;
    const int part = tid & 3;                     // h-slice index 0..3
    const int sb   = blockIdx.y;
    const int n    = blockIdx.x * TOKPB + (tid >> 2);

    for (int i = tid; i < DD * HH; i += TPB) Wx_s[i]  = W1[i];   // rows 0..31 of W1
    for (int i = tid; i < KK * HH; i += TPB) hkb_s[i] = g_hkb[sb * KK * HH + i];
    if (tid < HH) w2_s[tid] = W2[tid];
    __syncthreads();

    // full x row (32 floats) into registers (4 threads/token load redundantly; L1 hits)
    float xr[DD];
    const float4* xp = reinterpret_cast<const float4*>(x + ((size_t)sb * NTOK + n) * DD);
    #pragma unroll
    for (int i = 0; i < 8; i++) {
        float4 v = xp[i];
        xr[4 * i + 0] = v.x; xr[4 * i + 1] = v.y;
        xr[4 * i + 2] = v.z; xr[4 * i + 3] = v.w;
    }

    float acc[KK];
    #pragma unroll
    for (int k = 0; k < KK; k++) acc[k] = 0.f;

    const int h0 = part * 32;
    #pragma unroll 1
    for (int hc = h0; hc < h0 + 32; hc += 16) {
        // ---- hx chunk (8 f32x2 pairs) via packed FFMA2 ----
        u64 hx2[8];
        #pragma unroll
        for (int j = 0; j < 8; j++) hx2[j] = 0ull;

        #pragma unroll
        for (int d = 0; d < DD; d++) {
            u64 xd2 = pk2(xr[d], xr[d]);
            const ulonglong2* wrow = reinterpret_cast<const ulonglong2*>(&Wx_s[d * HH + hc]);
            #pragma unroll
            for (int q = 0; q < 4; q++) {
                ulonglong2 w = wrow[q];       // broadcast LDS.128 -> 2 f32x2 pairs
                hx2[2 * q + 0] = fma2(xd2, w.x, hx2[2 * q + 0]);
                hx2[2 * q + 1] = fma2(xd2, w.y, hx2[2 * q + 1]);
            }
        }

        float w2c[16];
        const float4* w2p = reinterpret_cast<const float4*>(&w2_s[hc]);
        #pragma unroll
        for (int q = 0; q < 4; q++) {
            float4 w = w2p[q];
            w2c[4 * q + 0] = w.x; w2c[4 * q + 1] = w.y;
            w2c[4 * q + 2] = w.z; w2c[4 * q + 3] = w.w;
        }

        // ---- k sweep: packed add, scalar tanh + fma ----
        #pragma unroll
        for (int k = 0; k < KK; k++) {
            const ulonglong2* hkp = reinterpret_cast<const ulonglong2*>(&hkb_s[k * HH + hc]);
            float a = acc[k];
            #pragma unroll
            for (int q = 0; q < 4; q++) {
                ulonglong2 hv = hkp[q];       // broadcast LDS.128
                u64 t0 = add2(hx2[2 * q + 0], hv.x);
                u64 t1 = add2(hx2[2 * q + 1], hv.y);
                float l0, hg0, l1, hg1;
                upk2(l0, hg0, t0);
                upk2(l1, hg1, t1);
                a = fmaf(tanhfast(l0),  w2c[4 * q + 0], a);
                a = fmaf(tanhfast(hg0), w2c[4 * q + 1], a);
                a = fmaf(tanhfast(l1),  w2c[4 * q + 2], a);
                a = fmaf(tanhfast(hg1), w2c[4 * q + 3], a);
            }
            acc[k] = a;
        }
    }

    // Combine partial gammas across the 4 lanes of this token (butterfly:
    // all 4 lanes end with the full sum).
    #pragma unroll
    for (int k = 0; k < KK; k++) {
        acc[k] += __shfl_xor_sync(0xffffffffu, acc[k], 1);
        acc[k] += __shfl_xor_sync(0xffffffffu, acc[k], 2);
    }

    // Softmax over K=16 in registers (b2 cancels); computed redundantly by
    // all 4 lanes, each writes its own quarter -> coalesced float4 stores.
    float m = acc[0];
    #pragma unroll
    for (int k = 1; k < KK; k++) m = fmaxf(m, acc[k]);
    float s = 0.f;
    #pragma unroll
    for (int k = 0; k < KK; k++) { acc[k] = __expf(acc[k] - m); s += acc[k]; }
    float inv = __fdividef(1.f, s);

    float4 v;
    v.x = acc[4 * part + 0] * inv; v.y = acc[4 * part + 1] * inv;
    v.z = acc[4 * part + 2] * inv; v.w = acc[4 * part + 3] * inv;
    reinterpret_cast<float4*>(out + ((size_t)sb * NTOK + n) * KK)[part] = v;
}

extern "C" void kernel_launch(void* const* d_in, const int* in_sizes, int n_in,
                              void* d_out, int out_size) {
    const float* x   = (const float*)d_in[0];
    const float* mu  = (const float*)d_in[1];
    const float* tau = (const float*)d_in[2];
    const float* W1  = (const float*)d_in[3];
    const float* b1  = (const float*)d_in[4];
    const float* W2  = (const float*)d_in[5];
    // d_in[6] = b2: cancels in softmax, unused.
    float* out = (float*)d_out;

    prep_kernel<<<dim3(KK, SB), HH>>>(mu, tau, W1, b1);
    main_kernel<<<dim3(NTOK / TOKPB, SB), TPB>>>(x, W1, W2, out);
}

// round 4
// speedup vs baseline: 3.4066x; 3.4066x over previous
#include <cuda_runtime.h>

#define SB   32      // S*B
#define NTOK 2048    // N
#define KK   16      // K
#define DD   32      // D
#define HH   128     // H

#define TPB   128    // threads per block (4 warps)
#define TOKPB 32     // tokens per block (1 per lane; warp = h-slice)

typedef unsigned long long u64;

// Scratch for hk[k,h] + b1[h] per (s,b). 32*16*128 floats = 256 KB.
__device__ float g_hkb[SB * KK * HH];

__device__ __forceinline__ float tanhfast(float v) {
    float y;
    asm("tanh.approx.f32 %0, %1;" : "=f"(y) : "f"(v));
    return y;
}
__device__ __forceinline__ u64 pk2(float lo, float hi) {
    u64 r; asm("mov.b64 %0, {%1, %2};" : "=l"(r) : "f"(lo), "f"(hi)); return r;
}
__device__ __forceinline__ void upk2(float& lo, float& hi, u64 v) {
    asm("mov.b64 {%0, %1}, %2;" : "=f"(lo), "=f"(hi) : "l"(v));
}
__device__ __forceinline__ u64 add2(u64 a, u64 b) {
    u64 r; asm("add.rn.f32x2 %0, %1, %2;" : "=l"(r) : "l"(a), "l"(b)); return r;
}
__device__ __forceinline__ u64 fma2(u64 a, u64 b, u64 c) {
    u64 r; asm("fma.rn.f32x2 %0, %1, %2, %3;" : "=l"(r) : "l"(a), "l"(b), "l"(c)); return r;
}

// ---------------------------------------------------------------------------
// Prep: hkb[sb,k,h] = sum_d mu[sb,k,d]*Wm[d,h] + tau[sb,k,d]*Wt[d,h] + b1[h]
// ---------------------------------------------------------------------------
__global__ void prep_kernel(const float* __restrict__ mu,
                            const float* __restrict__ tau,
                            const float* __restrict__ W1,
                            const float* __restrict__ b1) {
    int k  = blockIdx.x;
    int sb = blockIdx.y;
    int h  = threadIdx.x;
    const float* mur  = mu  + (sb * KK + k) * DD;
    const float* taur = tau + (sb * KK + k) * DD;
    float s = b1[h];
    #pragma unroll
    for (int d = 0; d < DD; d++) {
        s = fmaf(mur [d], W1[(DD     + d) * HH + h], s);
        s = fmaf(taur[d], W1[(2 * DD + d) * HH + h], s);
    }
    g_hkb[(sb * KK + k) * HH + h] = s;
}

// ---------------------------------------------------------------------------
// Main: block = 4 warps x 32 tokens. Warp w owns h-slice [32w, 32w+32);
// lane = token. All hot-loop LDS addresses are warp-uniform (broadcast).
// Partial gammas combined via smem, softmax via 4-lane shfl groups.
// ---------------------------------------------------------------------------
__global__ __launch_bounds__(TPB, 5)
void main_kernel(const float* __restrict__ x,
                 const float* __restrict__ W1,
                 const float* __restrict__ W2,
                 float* __restrict__ out) {
    __shared__ float Wx_s[DD * HH];             // 16 KB
    __shared__ float hkb_s[KK * HH];            //  8 KB
    __shared__ float w2_s[HH];                  // 0.5 KB
    __shared__ float part_s[4][TOKPB][KK];      //  8 KB partial gammas

    const int tid  = threadIdx.x;
    const int w    = tid >> 5;                  // warp id = h-slice
    const int lane = tid & 31;                  // token within block
    const int sb   = blockIdx.y;
    const int n    = blockIdx.x * TOKPB + lane;

    for (int i = tid; i < DD * HH; i += TPB) Wx_s[i]  = W1[i];   // rows 0..31 of W1
    for (int i = tid; i < KK * HH; i += TPB) hkb_s[i] = g_hkb[sb * KK * HH + i];
    if (tid < HH) w2_s[tid] = W2[tid];
    __syncthreads();

    // x row (32 floats) into registers; warps 1-3 hit L1 on the same lines.
    float xr[DD];
    const float4* xp = reinterpret_cast<const float4*>(x + ((size_t)sb * NTOK + n) * DD);
    #pragma unroll
    for (int i = 0; i < 8; i++) {
        float4 v = xp[i];
        xr[4 * i + 0] = v.x; xr[4 * i + 1] = v.y;
        xr[4 * i + 2] = v.z; xr[4 * i + 3] = v.w;
    }

    float acc[KK];
    #pragma unroll
    for (int k = 0; k < KK; k++) acc[k] = 0.f;

    const int h0 = w * 32;
    #pragma unroll 1
    for (int hc = h0; hc < h0 + 32; hc += 16) {
        // ---- hx chunk (8 f32x2 pairs) via packed FFMA2 ----
        u64 hx2[8];
        #pragma unroll
        for (int j = 0; j < 8; j++) hx2[j] = 0ull;

        #pragma unroll
        for (int d = 0; d < DD; d++) {
            u64 xd2 = pk2(xr[d], xr[d]);
            const ulonglong2* wrow = reinterpret_cast<const ulonglong2*>(&Wx_s[d * HH + hc]);
            #pragma unroll
            for (int q = 0; q < 4; q++) {
                ulonglong2 wv = wrow[q];      // warp-uniform broadcast LDS.128
                hx2[2 * q + 0] = fma2(xd2, wv.x, hx2[2 * q + 0]);
                hx2[2 * q + 1] = fma2(xd2, wv.y, hx2[2 * q + 1]);
            }
        }

        float w2c[16];
        const float4* w2p = reinterpret_cast<const float4*>(&w2_s[hc]);
        #pragma unroll
        for (int q = 0; q < 4; q++) {
            float4 wv = w2p[q];
            w2c[4 * q + 0] = wv.x; w2c[4 * q + 1] = wv.y;
            w2c[4 * q + 2] = wv.z; w2c[4 * q + 3] = wv.w;
        }

        // ---- k sweep: packed add, scalar tanh + fma ----
        #pragma unroll
        for (int k = 0; k < KK; k++) {
            const ulonglong2* hkp = reinterpret_cast<const ulonglong2*>(&hkb_s[k * HH + hc]);
            float a = acc[k];
            #pragma unroll
            for (int q = 0; q < 4; q++) {
                ulonglong2 hv = hkp[q];       // warp-uniform broadcast LDS.128
                u64 t0 = add2(hx2[2 * q + 0], hv.x);
                u64 t1 = add2(hx2[2 * q + 1], hv.y);
                float l0, hg0, l1, hg1;
                upk2(l0, hg0, t0);
                upk2(l1, hg1, t1);
                a = fmaf(tanhfast(l0),  w2c[4 * q + 0], a);
                a = fmaf(tanhfast(hg0), w2c[4 * q + 1], a);
                a = fmaf(tanhfast(l1),  w2c[4 * q + 2], a);
                a = fmaf(tanhfast(hg1), w2c[4 * q + 3], a);
            }
            acc[k] = a;
        }
    }

    // Stage partial gammas (per warp, per token) and combine across warps.
    {
        float4* ps = reinterpret_cast<float4*>(&part_s[w][lane][0]);
        #pragma unroll
        for (int q = 0; q < 4; q++) {
            float4 v;
            v.x = acc[4 * q + 0]; v.y = acc[4 * q + 1];
            v.z = acc[4 * q + 2]; v.w = acc[4 * q + 3];
            ps[q] = v;
        }
    }
    __syncthreads();

    // Reduce + softmax: thread t handles token (t>>2), k-quad (t&3).
    const int tok = tid >> 2;
    const int kq  = tid & 3;
    float4 g = reinterpret_cast<const float4*>(&part_s[0][tok][0])[kq];
    #pragma unroll
    for (int ww = 1; ww < 4; ww++) {
        float4 p = reinterpret_cast<const float4*>(&part_s[ww][tok][0])[kq];
        g.x += p.x; g.y += p.y; g.z += p.z; g.w += p.w;
    }

    // max over 16 k: local max of 4, butterfly across the 4 lanes of this token
    float m = fmaxf(fmaxf(g.x, g.y), fmaxf(g.z, g.w));
    m = fmaxf(m, __shfl_xor_sync(0xffffffffu, m, 1));
    m = fmaxf(m, __shfl_xor_sync(0xffffffffu, m, 2));

    float4 e;
    e.x = __expf(g.x - m); e.y = __expf(g.y - m);
    e.z = __expf(g.z - m); e.w = __expf(g.w - m);
    float s = e.x + e.y + e.z + e.w;
    s += __shfl_xor_sync(0xffffffffu, s, 1);
    s += __shfl_xor_sync(0xffffffffu, s, 2);
    float inv = __fdividef(1.f, s);

    const int ntok = blockIdx.x * TOKPB + tok;
    float4 o;
    o.x = e.x * inv; o.y = e.y * inv; o.z = e.z * inv; o.w = e.w * inv;
    reinterpret_cast<float4*>(out + ((size_t)sb * NTOK + ntok) * KK)[kq] = o;
}

extern "C" void kernel_launch(void* const* d_in, const int* in_sizes, int n_in,
                              void* d_out, int out_size) {
    const float* x   = (const float*)d_in[0];
    const float* mu  = (const float*)d_in[1];
    const float* tau = (const float*)d_in[2];
    const float* W1  = (const float*)d_in[3];
    const float* b1  = (const float*)d_in[4];
    const float* W2  = (const float*)d_in[5];
    // d_in[6] = b2: cancels in softmax, unused.
    float* out = (float*)d_out;

    prep_kernel<<<dim3(KK, SB), HH>>>(mu, tau, W1, b1);
    main_kernel<<<dim3(NTOK / TOKPB, SB), TPB>>>(x, W1, W2, out);
}

// round 5
// speedup vs baseline: 3.6703x; 1.0774x over previous
#include <cuda_runtime.h>

#define SB   32      // S*B
#define NTOK 2048    // N
#define KK   16      // K
#define DD   32      // D
#define HH   128     // H

#define TPB   128    // threads per block (4 warps)
#define TOKPB 32     // tokens per block (1 per lane; warp = h-slice of 32)

typedef unsigned long long u64;

// Scratch for hk[k,h] + b1[h] per (s,b). 32*16*128 floats = 256 KB.
__device__ float g_hkb[SB * KK * HH];

__device__ __forceinline__ float tanhfast(float v) {
    float y;
    asm("tanh.approx.f32 %0, %1;" : "=f"(y) : "f"(v));
    return y;
}
__device__ __forceinline__ u64 pk2(float lo, float hi) {
    u64 r; asm("mov.b64 %0, {%1, %2};" : "=l"(r) : "f"(lo), "f"(hi)); return r;
}
__device__ __forceinline__ void upk2(float& lo, float& hi, u64 v) {
    asm("mov.b64 {%0, %1}, %2;" : "=f"(lo), "=f"(hi) : "l"(v));
}
__device__ __forceinline__ u64 add2(u64 a, u64 b) {
    u64 r; asm("add.rn.f32x2 %0, %1, %2;" : "=l"(r) : "l"(a), "l"(b)); return r;
}
__device__ __forceinline__ u64 fma2(u64 a, u64 b, u64 c) {
    u64 r; asm("fma.rn.f32x2 %0, %1, %2, %3;" : "=l"(r) : "l"(a), "l"(b), "l"(c)); return r;
}

// ---------------------------------------------------------------------------
// Prep: hkb[sb,k,h] = sum_d mu[sb,k,d]*Wm[d,h] + tau[sb,k,d]*Wt[d,h] + b1[h]
// ---------------------------------------------------------------------------
__global__ void prep_kernel(const float* __restrict__ mu,
                            const float* __restrict__ tau,
                            const float* __restrict__ W1,
                            const float* __restrict__ b1) {
    int k  = blockIdx.x;
    int sb = blockIdx.y;
    int h  = threadIdx.x;
    const float* mur  = mu  + (sb * KK + k) * DD;
    const float* taur = tau + (sb * KK + k) * DD;
    float s = b1[h];
    #pragma unroll
    for (int d = 0; d < DD; d++) {
        s = fmaf(mur [d], W1[(DD     + d) * HH + h], s);
        s = fmaf(taur[d], W1[(2 * DD + d) * HH + h], s);
    }
    g_hkb[(sb * KK + k) * HH + h] = s;
}

// ---------------------------------------------------------------------------
// Main: block = 4 warps x 32 tokens. Warp w owns h-slice [32w, 32w+32);
// lane = token. Thread program is two fully-unrolled straight-line phases:
//   Phase A: hx2[16] (32 h) via 16 independent FFMA2 chains over d.
//   Phase B: for each k: 8 broadcast LDS.128 + 16 ADD2 + 32 tanh + 32 FFMA
//            into 4 partial accumulators (no serial chain).
// Partial gammas combined via padded smem, softmax via 4-lane shfl groups.
// ---------------------------------------------------------------------------
__global__ __launch_bounds__(TPB, 5)
void main_kernel(const float* __restrict__ x,
                 const float* __restrict__ W1,
                 const float* __restrict__ W2,
                 float* __restrict__ out) {
    __shared__ float Wx_s[DD * HH];             // 16 KB
    __shared__ float hkb_s[KK * HH];            //  8 KB
    __shared__ float w2_s[HH];                  // 0.5 KB
    __shared__ float part_s[4][TOKPB][KK + 1];  //  8.5 KB, pad 17 -> conflict-free

    const int tid  = threadIdx.x;
    const int w    = tid >> 5;                  // warp id = h-slice
    const int lane = tid & 31;                  // token within block
    const int sb   = blockIdx.y;
    const int n    = blockIdx.x * TOKPB + lane;

    for (int i = tid; i < DD * HH; i += TPB) Wx_s[i]  = W1[i];   // rows 0..31 of W1
    for (int i = tid; i < KK * HH; i += TPB) hkb_s[i] = g_hkb[sb * KK * HH + i];
    if (tid < HH) w2_s[tid] = W2[tid];
    __syncthreads();

    // x row (32 floats) into registers
    float xr[DD];
    const float4* xp = reinterpret_cast<const float4*>(x + ((size_t)sb * NTOK + n) * DD);
    #pragma unroll
    for (int i = 0; i < 8; i++) {
        float4 v = xp[i];
        xr[4 * i + 0] = v.x; xr[4 * i + 1] = v.y;
        xr[4 * i + 2] = v.z; xr[4 * i + 3] = v.w;
    }

    const int h0 = w * 32;

    // ---- Phase A: hx for the full 32-h slice (16 f32x2 chains) ----
    u64 hx2[16];
    #pragma unroll
    for (int j = 0; j < 16; j++) hx2[j] = 0ull;

    #pragma unroll
    for (int d = 0; d < DD; d++) {
        u64 xd2 = pk2(xr[d], xr[d]);
        const ulonglong2* wrow = reinterpret_cast<const ulonglong2*>(&Wx_s[d * HH + h0]);
        #pragma unroll
        for (int q = 0; q < 8; q++) {
            ulonglong2 wv = wrow[q];          // warp-uniform broadcast LDS.128
            hx2[2 * q + 0] = fma2(xd2, wv.x, hx2[2 * q + 0]);
            hx2[2 * q + 1] = fma2(xd2, wv.y, hx2[2 * q + 1]);
        }
    }

    // W2 slice (32 floats) into registers
    float w2c[32];
    {
        const float4* w2p = reinterpret_cast<const float4*>(&w2_s[h0]);
        #pragma unroll
        for (int q = 0; q < 8; q++) {
            float4 wv = w2p[q];
            w2c[4 * q + 0] = wv.x; w2c[4 * q + 1] = wv.y;
            w2c[4 * q + 2] = wv.z; w2c[4 * q + 3] = wv.w;
        }
    }

    // ---- Phase B: k-sweep over full 32-h slice, 4 partial accumulators ----
    float acc[KK];
    #pragma unroll
    for (int k = 0; k < KK; k++) {
        const ulonglong2* hkp = reinterpret_cast<const ulonglong2*>(&hkb_s[k * HH + h0]);
        float a0 = 0.f, a1 = 0.f, a2 = 0.f, a3 = 0.f;
        #pragma unroll
        for (int q = 0; q < 8; q++) {
            ulonglong2 hv = hkp[q];           // warp-uniform broadcast LDS.128
            u64 t0 = add2(hx2[2 * q + 0], hv.x);
            u64 t1 = add2(hx2[2 * q + 1], hv.y);
            float l0, g0, l1, g1;
            upk2(l0, g0, t0);
            upk2(l1, g1, t1);
            a0 = fmaf(tanhfast(l0), w2c[4 * q + 0], a0);
            a1 = fmaf(tanhfast(g0), w2c[4 * q + 1], a1);
            a2 = fmaf(tanhfast(l1), w2c[4 * q + 2], a2);
            a3 = fmaf(tanhfast(g1), w2c[4 * q + 3], a3);
        }
        acc[k] = (a0 + a1) + (a2 + a3);
    }

    // Stage partial gammas (scalar, padded row of 17 -> conflict-free).
    #pragma unroll
    for (int k = 0; k < KK; k++) part_s[w][lane][k] = acc[k];
    __syncthreads();

    // Reduce + softmax: thread t handles token (t>>2), k-quad (t&3).
    const int tok = tid >> 2;
    const int kq  = tid & 3;
    float g[4];
    #pragma unroll
    for (int j = 0; j < 4; j++) {
        int k = 4 * kq + j;
        g[j] = ((part_s[0][tok][k] + part_s[1][tok][k]) +
                (part_s[2][tok][k] + part_s[3][tok][k]));
    }

    // max over 16 k: local max of 4, butterfly across the 4 lanes of this token
    float m = fmaxf(fmaxf(g[0], g[1]), fmaxf(g[2], g[3]));
    m = fmaxf(m, __shfl_xor_sync(0xffffffffu, m, 1));
    m = fmaxf(m, __shfl_xor_sync(0xffffffffu, m, 2));

    float e0 = __expf(g[0] - m), e1 = __expf(g[1] - m);
    float e2 = __expf(g[2] - m), e3 = __expf(g[3] - m);
    float s = (e0 + e1) + (e2 + e3);
    s += __shfl_xor_sync(0xffffffffu, s, 1);
    s += __shfl_xor_sync(0xffffffffu, s, 2);
    float inv = __fdividef(1.f, s);

    const int ntok = blockIdx.x * TOKPB + tok;
    float4 o;
    o.x = e0 * inv; o.y = e1 * inv; o.z = e2 * inv; o.w = e3 * inv;
    reinterpret_cast<float4*>(out + ((size_t)sb * NTOK + ntok) * KK)[kq] = o;
}

extern "C" void kernel_launch(void* const* d_in, const int* in_sizes, int n_in,
                              void* d_out, int out_size) {
    const float* x   = (const float*)d_in[0];
    const float* mu  = (const float*)d_in[1];
    const float* tau = (const float*)d_in[2];
    const float* W1  = (const float*)d_in[3];
    const float* b1  = (const float*)d_in[4];
    const float* W2  = (const float*)d_in[5];
    // d_in[6] = b2: cancels in softmax, unused.
    float* out = (float*)d_out;

    prep_kernel<<<dim3(KK, SB), HH>>>(mu, tau, W1, b1);
    main_kernel<<<dim3(NTOK / TOKPB, SB), TPB>>>(x, W1, W2, out);
}